// round 3
// baseline (speedup 1.0000x reference)
#include <cuda_runtime.h>
#include <cuda_bf16.h>
#include <cstdint>

// Problem constants
#define D      64
#define K      1024
#define HW     4096        // 64*64
#define NROWS  131072      // 32*64*64
#define MT     128         // rows per block
#define NT     128         // codes per tile
#define XP2    130         // xs2 pitch in float2 units (130*8=1040B: rotates banks by 4/row)

// Output layout (concatenated, float32): quantized_out (b,c,h,w), loss (b,h,w,c), idx (b,h,w)
#define LOFF   8388608
#define IOFF   16777216

// Scratch (no cudaMalloc allowed)
__device__ float g_eT[D * K];   // embedding transposed [d][k]
__device__ float g_e2[K];       // ||e_k||^2

// ---------------------------------------------------------------------------
// Prep: transpose embedding + row norms. Tiny, runs in a few us.
// ---------------------------------------------------------------------------
__global__ void vq_prep_kernel(const float* __restrict__ emb) {
    int k = blockIdx.x * blockDim.x + threadIdx.x;
    if (k < K) {
        float s = 0.0f;
#pragma unroll
        for (int d = 0; d < D; ++d) {
            float v = emb[k * D + d];
            g_eT[d * K + k] = v;
            s = fmaf(v, v, s);
        }
        g_e2[k] = s;
    }
}

// ---------------------------------------------------------------------------
// Main kernel. 128m x 128n per block, 256 threads, 8m x 8n per thread.
// f32x2 pairs packed along n: e operand loads as natural adjacent pairs
// (no movs), x operand loads pre-duplicated from xs2 (broadcast -> crossbar-free).
// ---------------------------------------------------------------------------
extern __shared__ float sm[];

__global__ __launch_bounds__(256, 2) void vq_main_kernel(
    const float* __restrict__ x,     // [b, c, h, w] fp32
    const float* __restrict__ emb,   // [K, D] fp32
    float* __restrict__ out)
{
    float2* xs2 = (float2*)sm;            // [64][XP2]  x tile, each value duplicated {v,v}
    float*  es  = sm + 2 * D * XP2;       // [64][128]  e tile, d-major; reused as reduce scratch
    __shared__ float rs[MT];              // row sums ||x||^2
    __shared__ float e2s[NT];             // code norms for current tile
    __shared__ int   idxRow[MT];          // final argmin per row

    const int tid = threadIdx.x;
    const int p0  = blockIdx.x * MT;      // first global row of this block
    const int b   = p0 >> 12;             // p0 / 4096
    const int s0  = p0 & 4095;            // spatial offset within image
    const float* xbase = x + (size_t)b * 64 * HW + s0;

    // ---- load x tile (dup pairs): for each channel d, 128 contiguous floats ----
#pragma unroll
    for (int i = 0; i < 32; ++i) {
        int idx = tid + i * 256;
        int d = idx >> 7, m = idx & 127;
        float v = xbase[d * HW + m];
        xs2[d * XP2 + m] = make_float2(v, v);
    }
    __syncthreads();

    // ---- per-row ||x||^2 (sequential d; order matches reference-benign shift) ----
    if (tid < MT) {
        float s = 0.0f;
#pragma unroll
        for (int d = 0; d < D; ++d) {
            float v = xs2[d * XP2 + tid].x;
            s = fmaf(v, v, s);
        }
        rs[tid] = s;
    }

    const int tx = tid & 15;   // n-group: codes tx*8 .. tx*8+7
    const int ty = tid >> 4;   // m-group: rows  ty*8 .. ty*8+7

    float bestv[8];
    int   besti[8];
#pragma unroll
    for (int i = 0; i < 8; ++i) { bestv[i] = 3.4e38f; besti[i] = 0; }

    for (int nt = 0; nt < K / NT; ++nt) {
        __syncthreads();   // protect es before overwrite (publishes rs on first iter)
        // ---- load e tile [d][n] (coalesced from pre-transposed g_eT) ----
        const float* eTt = g_eT + nt * NT;
#pragma unroll
        for (int i = 0; i < 32; ++i) {
            int idx = tid + i * 256;
            int d = idx >> 7, n = idx & 127;
            es[d * NT + n] = eTt[d * K + n];
        }
        if (tid < NT) e2s[tid] = g_e2[nt * NT + tid];
        __syncthreads();   // es, e2s (and rs) visible

        // ---- 8x8 register tile: acc[mi][np], f32x2 pairs along n ----
        unsigned long long acc[8][4];
#pragma unroll
        for (int mi = 0; mi < 8; ++mi)
#pragma unroll
            for (int np = 0; np < 4; ++np) acc[mi][np] = 0ULL;

#pragma unroll 4
        for (int d = 0; d < D; ++d) {
            // x: 8 duplicated pairs, broadcast loads (2 distinct addrs per warp)
            const float2* xrow = xs2 + d * XP2 + ty * 8;
            ulonglong2 xA = *(const ulonglong2*)(xrow);
            ulonglong2 xB = *(const ulonglong2*)(xrow + 2);
            ulonglong2 xC = *(const ulonglong2*)(xrow + 4);
            ulonglong2 xD = *(const ulonglong2*)(xrow + 6);
            unsigned long long ax[8] = { xA.x, xA.y, xB.x, xB.y,
                                         xC.x, xC.y, xD.x, xD.y };

            // e: 8 codes = 4 natural adjacent pairs, no duplication needed
            const ulonglong2* ep = (const ulonglong2*)(es + d * NT + tx * 8);
            ulonglong2 e0 = ep[0], e1 = ep[1];
            unsigned long long en[4] = { e0.x, e0.y, e1.x, e1.y };

#pragma unroll
            for (int mi = 0; mi < 8; ++mi)
#pragma unroll
                for (int np = 0; np < 4; ++np)
                    asm("fma.rn.f32x2 %0, %1, %2, %0;"
                        : "+l"(acc[mi][np]) : "l"(ax[mi]), "l"(en[np]));
        }

        // ---- distances + running argmin (ascending n, strict < keeps first) ----
#pragma unroll
        for (int mi = 0; mi < 8; ++mi) {
            float r = rs[ty * 8 + mi];
#pragma unroll
            for (int np = 0; np < 4; ++np) {
                int n0 = nt * NT + tx * 8 + 2 * np;
                float2 dv = *(float2*)&acc[mi][np];
                // reference association: (||x||^2 + ||e||^2) - 2*dot, one rounding each
                float t0 = r + e2s[tx * 8 + 2 * np];
                float t1 = r + e2s[tx * 8 + 2 * np + 1];
                float d0 = fmaf(dv.x, -2.0f, t0);
                float d1 = fmaf(dv.y, -2.0f, t1);
                if (d0 < bestv[mi]) { bestv[mi] = d0; besti[mi] = n0; }
                if (d1 < bestv[mi]) { bestv[mi] = d1; besti[mi] = n0 + 1; }
            }
        }
    }

    // ---- cross-thread argmin reduce (reuse es as scratch) ----
    __syncthreads();
    float* redv = es;                 // [128][16]
    int*   redi = (int*)(es + 2048);  // [128][16]
#pragma unroll
    for (int i = 0; i < 8; ++i) {
        int m = ty * 8 + i;
        redv[m * 16 + tx] = bestv[i];
        redi[m * 16 + tx] = besti[i];
    }
    __syncthreads();
    if (tid < MT) {
        float bv = redv[tid * 16];
        int   bi = redi[tid * 16];
#pragma unroll
        for (int t = 1; t < 16; ++t) {
            float v = redv[tid * 16 + t];
            int   ii = redi[tid * 16 + t];
            if (v < bv || (v == bv && ii < bi)) { bv = v; bi = ii; }
        }
        idxRow[tid] = bi;
        out[IOFF + p0 + tid] = (float)bi;   // idx as float (output dtype f32)
    }
    __syncthreads();

    // ---- loss (b,h,w,c): 64 contiguous floats per row ----
#pragma unroll
    for (int i = 0; i < 32; ++i) {
        int idx = tid + i * 256;
        int m = idx >> 6, c = idx & 63;
        float xv = xs2[c * XP2 + m].x;
        float ev = emb[idxRow[m] * D + c];
        float df = ev - xv;                 // (quantized - x), one rounding
        float t  = df * df;
        out[LOFF + (size_t)(p0 + m) * 64 + c] = t + 0.25f * t;  // == round(1.25*t)
    }

    // ---- quantized_out (b,c,h,w): per channel, 128 contiguous floats ----
#pragma unroll
    for (int i = 0; i < 32; ++i) {
        int idx = tid + i * 256;
        int c = idx >> 7, m = idx & 127;
        float xv = xs2[c * XP2 + m].x;
        float ev = emb[idxRow[m] * D + c];
        // straight-through: x + (q - x), NOT q (last-ulp fidelity to reference)
        out[(size_t)(b * 64 + c) * HW + s0 + m] = xv + (ev - xv);
    }
}

// ---------------------------------------------------------------------------
extern "C" void kernel_launch(void* const* d_in, const int* in_sizes, int n_in,
                              void* d_out, int out_size)
{
    const float* x_in = (const float*)d_in[0];   // inputs  [32,64,64,64]
    const float* emb  = (const float*)d_in[1];   // embedding [1024,64]
    float* out = (float*)d_out;

    static bool attr_set = false;
    // xs2: 64*130*8 = 66560B, es: 64*128*4 = 32768B -> 99328B (2 CTAs fit in 228KB)
    size_t smem_bytes = (size_t)(2 * D * XP2 + D * NT) * sizeof(float);
    if (!attr_set) {
        cudaFuncSetAttribute(vq_main_kernel,
                             cudaFuncAttributeMaxDynamicSharedMemorySize,
                             (int)smem_bytes);
        attr_set = true;
    }

    vq_prep_kernel<<<4, 256>>>(emb);
    vq_main_kernel<<<NROWS / MT, 256, smem_bytes>>>(x_in, emb, out);
}

// round 4
// speedup vs baseline: 1.2163x; 1.2163x over previous
#include <cuda_runtime.h>
#include <cuda_bf16.h>
#include <cstdint>

// Problem constants
#define D      64
#define K      1024
#define HW     4096        // 64*64
#define NROWS  131072      // 32*64*64
#define MT     128         // rows per block
#define NT     128         // codes per tile
#define XPITCH 132         // padded pitch for xs (132*4=528B, 16B-multiple)
#define ES_TILE 8192       // 64*128 floats per e tile

// Output layout (concatenated, float32): quantized_out (b,c,h,w), loss (b,h,w,c), idx (b,h,w)
#define LOFF   8388608
#define IOFF   16777216

// Scratch (no cudaMalloc allowed)
__device__ float g_eT[D * K];   // embedding transposed [d][k]
__device__ float g_e2[K];       // ||e_k||^2

__device__ __forceinline__ void cp_async16(uint32_t saddr, const void* gaddr) {
    asm volatile("cp.async.cg.shared.global [%0], [%1], 16;" :: "r"(saddr), "l"(gaddr) : "memory");
}
__device__ __forceinline__ void cp_commit() {
    asm volatile("cp.async.commit_group;" ::: "memory");
}

// ---------------------------------------------------------------------------
// Prep: transpose embedding + row norms. Tiny, runs in a few us.
// ---------------------------------------------------------------------------
__global__ void vq_prep_kernel(const float* __restrict__ emb) {
    int k = blockIdx.x * blockDim.x + threadIdx.x;
    if (k < K) {
        float s = 0.0f;
#pragma unroll
        for (int d = 0; d < D; ++d) {
            float v = emb[k * D + d];
            g_eT[d * K + k] = v;
            s = fmaf(v, v, s);
        }
        g_e2[k] = s;
    }
}

// ---------------------------------------------------------------------------
// Main kernel. 128m x 128n per block, 256 threads, 8m x 8n per thread,
// f32x2 pairs packed along m (R2 inner loop). Double-buffered e tiles via
// cp.async so tile loads overlap compute.
// ---------------------------------------------------------------------------
extern __shared__ float sm[];

__global__ __launch_bounds__(256, 2) void vq_main_kernel(
    const float* __restrict__ x,     // [b, c, h, w] fp32
    const float* __restrict__ emb,   // [K, D] fp32
    float* __restrict__ out)
{
    float* xs = sm;                       // [64][XPITCH]
    float* es = sm + D * XPITCH;          // [2][64][128] double-buffered e tiles
    __shared__ float rs[MT];              // row sums ||x||^2
    __shared__ float e2s[2][NT];          // code norms (double-buffered)
    __shared__ int   idxRow[MT];          // final argmin per row

    const int tid = threadIdx.x;
    const int p0  = blockIdx.x * MT;
    const int b   = p0 >> 12;
    const int s0  = p0 & 4095;
    const float* xbase = x + (size_t)b * 64 * HW + s0;

    const uint32_t es_u32  = (uint32_t)__cvta_generic_to_shared(es);
    const uint32_t e2s_u32 = (uint32_t)__cvta_generic_to_shared(e2s);

    // ---- prefetch e tile 0 ----
    {
        const float* src = g_eT;            // tile 0 at column offset 0
#pragma unroll
        for (int i = 0; i < 8; ++i) {
            int f = tid + i * 256;          // 2048 float4s total
            int d = f >> 5, nf = f & 31;
            cp_async16(es_u32 + (uint32_t)(d * NT + nf * 4) * 4, src + d * K + nf * 4);
        }
        if (tid < 32)
            cp_async16(e2s_u32 + (uint32_t)(tid * 4) * 4, g_e2 + tid * 4);
        cp_commit();
    }

    // ---- load x tile with float4: per channel d, 128 contiguous floats ----
#pragma unroll
    for (int i = 0; i < 8; ++i) {
        int f = tid + i * 256;              // 2048 float4s
        int d = f >> 5, mf = f & 31;
        float4 v = *(const float4*)(xbase + d * HW + mf * 4);
        *(float4*)(xs + d * XPITCH + mf * 4) = v;
    }
    __syncthreads();

    // ---- per-row ||x||^2 (sequential d; uniform per-row shift, order benign) ----
    if (tid < MT) {
        float s = 0.0f;
#pragma unroll
        for (int d = 0; d < D; ++d) {
            float v = xs[d * XPITCH + tid];
            s = fmaf(v, v, s);
        }
        rs[tid] = s;
    }

    const int tx = tid & 15;   // n-group: codes tx*8 .. tx*8+7
    const int ty = tid >> 4;   // m-group: rows  ty*8 .. ty*8+7

    float bestv[8];
    int   besti[8];
#pragma unroll
    for (int i = 0; i < 8; ++i) { bestv[i] = 3.4e38f; besti[i] = 0; }

    for (int nt = 0; nt < K / NT; ++nt) {
        const int buf = nt & 1;
        __syncthreads();   // all warps done with tile nt-1 -> buffer buf^1 free (also publishes rs/xs on nt=0)

        if (nt < K / NT - 1) {
            // prefetch tile nt+1 into the other buffer
            const float* src = g_eT + (nt + 1) * NT;
            uint32_t dst = es_u32 + (uint32_t)(buf ^ 1) * ES_TILE * 4;
#pragma unroll
            for (int i = 0; i < 8; ++i) {
                int f = tid + i * 256;
                int d = f >> 5, nf = f & 31;
                cp_async16(dst + (uint32_t)(d * NT + nf * 4) * 4, src + d * K + nf * 4);
            }
            if (tid < 32)
                cp_async16(e2s_u32 + (uint32_t)((buf ^ 1) * NT + tid * 4) * 4,
                           g_e2 + (nt + 1) * NT + tid * 4);
            cp_commit();
            asm volatile("cp.async.wait_group 1;" ::: "memory");   // tile nt complete
        } else {
            asm volatile("cp.async.wait_group 0;" ::: "memory");
        }
        __syncthreads();   // tile nt visible to all warps

        const float* esb = es + buf * ES_TILE;
        const float* e2b = e2s[buf];

        // ---- 8x8 register tile, f32x2 packed along m (R2 inner loop) ----
        unsigned long long acc[4][8];
#pragma unroll
        for (int mp = 0; mp < 4; ++mp)
#pragma unroll
            for (int j = 0; j < 8; ++j) acc[mp][j] = 0ULL;

#pragma unroll 4
        for (int d = 0; d < D; ++d) {
            const float* xrow = xs + d * XPITCH + ty * 8;
            ulonglong2 xA = *(const ulonglong2*)(xrow);       // rows (0,1),(2,3)
            ulonglong2 xB = *(const ulonglong2*)(xrow + 4);   // rows (4,5),(6,7)
            unsigned long long ax[4] = { xA.x, xA.y, xB.x, xB.y };

            const float4* ep = (const float4*)(esb + d * NT + tx * 8);
            float4 e0 = ep[0], e1 = ep[1];
            float ev[8] = { e0.x, e0.y, e0.z, e0.w, e1.x, e1.y, e1.z, e1.w };
#pragma unroll
            for (int j = 0; j < 8; ++j) {
                unsigned long long bv;
                asm("mov.b64 %0, {%1, %1};" : "=l"(bv) : "f"(ev[j]));
#pragma unroll
                for (int mp = 0; mp < 4; ++mp)
                    asm("fma.rn.f32x2 %0, %1, %2, %0;"
                        : "+l"(acc[mp][j]) : "l"(ax[mp]), "l"(bv));
            }
        }

        // ---- distances + running argmin (ascending n, strict < keeps first) ----
#pragma unroll
        for (int j = 0; j < 8; ++j) {
            int n = nt * NT + tx * 8 + j;
            float e2 = e2b[tx * 8 + j];
#pragma unroll
            for (int mp = 0; mp < 4; ++mp) {
                float2 dv = *(float2*)&acc[mp][j];
                // reference association: (||x||^2 + ||e||^2) - 2*dot, one rounding each
                float t0 = rs[ty * 8 + 2 * mp]     + e2;
                float t1 = rs[ty * 8 + 2 * mp + 1] + e2;
                float d0 = fmaf(dv.x, -2.0f, t0);
                float d1 = fmaf(dv.y, -2.0f, t1);
                if (d0 < bestv[2 * mp])     { bestv[2 * mp]     = d0; besti[2 * mp]     = n; }
                if (d1 < bestv[2 * mp + 1]) { bestv[2 * mp + 1] = d1; besti[2 * mp + 1] = n; }
            }
        }
    }

    // ---- cross-thread argmin reduce (reuse es buffer 0 as scratch) ----
    __syncthreads();
    float* redv = es;                 // [128][16]
    int*   redi = (int*)(es + 2048);  // [128][16]
#pragma unroll
    for (int i = 0; i < 8; ++i) {
        int m = ty * 8 + i;
        redv[m * 16 + tx] = bestv[i];
        redi[m * 16 + tx] = besti[i];
    }
    __syncthreads();
    if (tid < MT) {
        float bv = redv[tid * 16];
        int   bi = redi[tid * 16];
#pragma unroll
        for (int t = 1; t < 16; ++t) {
            float v = redv[tid * 16 + t];
            int   ii = redi[tid * 16 + t];
            if (v < bv || (v == bv && ii < bi)) { bv = v; bi = ii; }
        }
        idxRow[tid] = bi;
        out[IOFF + p0 + tid] = (float)bi;   // idx as float (output dtype f32)
    }
    __syncthreads();

    // ---- loss (b,h,w,c): 64 contiguous floats per row ----
#pragma unroll
    for (int i = 0; i < 32; ++i) {
        int idx = tid + i * 256;
        int m = idx >> 6, c = idx & 63;
        float xv = xs[c * XPITCH + m];
        float ev = emb[idxRow[m] * D + c];
        float df = ev - xv;                 // (quantized - x), one rounding
        float t  = df * df;
        out[LOFF + (size_t)(p0 + m) * 64 + c] = t + 0.25f * t;  // == round(1.25*t)
    }

    // ---- quantized_out (b,c,h,w): per channel, 128 contiguous floats ----
#pragma unroll
    for (int i = 0; i < 32; ++i) {
        int idx = tid + i * 256;
        int c = idx >> 7, m = idx & 127;
        float xv = xs[c * XPITCH + m];
        float ev = emb[idxRow[m] * D + c];
        // straight-through: x + (q - x), NOT q (last-ulp fidelity to reference)
        out[(size_t)(b * 64 + c) * HW + s0 + m] = xv + (ev - xv);
    }
}

// ---------------------------------------------------------------------------
extern "C" void kernel_launch(void* const* d_in, const int* in_sizes, int n_in,
                              void* d_out, int out_size)
{
    const float* x_in = (const float*)d_in[0];   // inputs  [32,64,64,64]
    const float* emb  = (const float*)d_in[1];   // embedding [1024,64]
    float* out = (float*)d_out;

    static bool attr_set = false;
    // xs: 64*132*4 = 33792B, es: 2*8192*4 = 65536B -> 99328B/CTA (2 CTAs fit)
    size_t smem_bytes = (size_t)(D * XPITCH + 2 * ES_TILE) * sizeof(float);
    if (!attr_set) {
        cudaFuncSetAttribute(vq_main_kernel,
                             cudaFuncAttributeMaxDynamicSharedMemorySize,
                             (int)smem_bytes);
        attr_set = true;
    }

    vq_prep_kernel<<<4, 256>>>(emb);
    vq_main_kernel<<<NROWS / MT, 256, smem_bytes>>>(x_in, emb, out);
}

// round 5
// speedup vs baseline: 1.2402x; 1.0196x over previous
#include <cuda_runtime.h>
#include <cuda_bf16.h>
#include <cstdint>

// Problem constants
#define D      64
#define K      1024
#define HW     4096        // 64*64
#define NROWS  131072      // 32*64*64
#define MT     128         // rows per block
#define NT     64          // codes per tile (16 tiles)
#define XPITCH 132         // padded pitch for xs (132*4=528B, 16B-multiple)
#define ES_TILE 4096       // 64*64 floats per e tile

// Output layout (concatenated, float32): quantized_out (b,c,h,w), loss (b,h,w,c), idx (b,h,w)
#define LOFF   8388608
#define IOFF   16777216

// Scratch (no cudaMalloc allowed)
__device__ float g_eT[D * K];   // embedding transposed [d][k]
__device__ float g_e2[K];       // ||e_k||^2

__device__ __forceinline__ void cp_async16(uint32_t saddr, const void* gaddr) {
    asm volatile("cp.async.cg.shared.global [%0], [%1], 16;" :: "r"(saddr), "l"(gaddr) : "memory");
}
__device__ __forceinline__ void cp_commit() {
    asm volatile("cp.async.commit_group;" ::: "memory");
}

// ---------------------------------------------------------------------------
// Prep: transpose embedding + row norms. Tiny, runs in a few us.
// ---------------------------------------------------------------------------
__global__ void vq_prep_kernel(const float* __restrict__ emb) {
    int k = blockIdx.x * blockDim.x + threadIdx.x;
    if (k < K) {
        float s = 0.0f;
#pragma unroll
        for (int d = 0; d < D; ++d) {
            float v = emb[k * D + d];
            g_eT[d * K + k] = v;
            s = fmaf(v, v, s);
        }
        g_e2[k] = s;
    }
}

// ---------------------------------------------------------------------------
// Main kernel. 128m x 64n per block, 256 threads, 8m x 4n per thread,
// f32x2 pairs packed along m. Double-buffered e tiles via cp.async.
// __launch_bounds__(256, 3): ~85 regs -> 3 CTAs (24 warps) per SM.
// ---------------------------------------------------------------------------
extern __shared__ float sm[];

__global__ __launch_bounds__(256, 3) void vq_main_kernel(
    const float* __restrict__ x,     // [b, c, h, w] fp32
    const float* __restrict__ emb,   // [K, D] fp32
    float* __restrict__ out)
{
    float* xs = sm;                       // [64][XPITCH]
    float* es = sm + D * XPITCH;          // [2][64][64] double-buffered e tiles
    __shared__ float rs[MT];              // row sums ||x||^2
    __shared__ float e2s[2][NT];          // code norms (double-buffered)
    __shared__ int   idxRow[MT];          // final argmin per row

    const int tid = threadIdx.x;
    const int p0  = blockIdx.x * MT;
    const int b   = p0 >> 12;
    const int s0  = p0 & 4095;
    const float* xbase = x + (size_t)b * 64 * HW + s0;

    const uint32_t es_u32  = (uint32_t)__cvta_generic_to_shared(es);
    const uint32_t e2s_u32 = (uint32_t)__cvta_generic_to_shared(e2s);

    // ---- prefetch e tile 0 (1024 float4s, 4 per thread) ----
    {
        const float* src = g_eT;            // tile 0 at column offset 0
#pragma unroll
        for (int i = 0; i < 4; ++i) {
            int f = tid + i * 256;          // 16 float4 per d-row
            int d = f >> 4, nf = f & 15;
            cp_async16(es_u32 + (uint32_t)(d * NT + nf * 4) * 4, src + d * K + nf * 4);
        }
        if (tid < 16)
            cp_async16(e2s_u32 + (uint32_t)(tid * 4) * 4, g_e2 + tid * 4);
        cp_commit();
    }

    // ---- load x tile with float4: per channel d, 128 contiguous floats ----
#pragma unroll
    for (int i = 0; i < 8; ++i) {
        int f = tid + i * 256;              // 2048 float4s
        int d = f >> 5, mf = f & 31;
        float4 v = *(const float4*)(xbase + d * HW + mf * 4);
        *(float4*)(xs + d * XPITCH + mf * 4) = v;
    }
    __syncthreads();

    // ---- per-row ||x||^2 (sequential d; uniform per-row shift, order benign) ----
    if (tid < MT) {
        float s = 0.0f;
#pragma unroll
        for (int d = 0; d < D; ++d) {
            float v = xs[d * XPITCH + tid];
            s = fmaf(v, v, s);
        }
        rs[tid] = s;
    }

    const int tx = tid & 15;   // n-group: codes tx*4 .. tx*4+3 within tile
    const int ty = tid >> 4;   // m-group: rows  ty*8 .. ty*8+7

    float bestv[8];
    int   besti[8];
#pragma unroll
    for (int i = 0; i < 8; ++i) { bestv[i] = 3.4e38f; besti[i] = 0; }

    for (int nt = 0; nt < K / NT; ++nt) {
        const int buf = nt & 1;
        __syncthreads();   // all warps done with tile nt-1 -> other buffer free (publishes rs/xs on nt=0)

        if (nt < K / NT - 1) {
            // prefetch tile nt+1 into the other buffer
            const float* src = g_eT + (nt + 1) * NT;
            uint32_t dst = es_u32 + (uint32_t)(buf ^ 1) * ES_TILE * 4;
#pragma unroll
            for (int i = 0; i < 4; ++i) {
                int f = tid + i * 256;
                int d = f >> 4, nf = f & 15;
                cp_async16(dst + (uint32_t)(d * NT + nf * 4) * 4, src + d * K + nf * 4);
            }
            if (tid < 16)
                cp_async16(e2s_u32 + (uint32_t)((buf ^ 1) * NT + tid * 4) * 4,
                           g_e2 + (nt + 1) * NT + tid * 4);
            cp_commit();
            asm volatile("cp.async.wait_group 1;" ::: "memory");   // tile nt complete
        } else {
            asm volatile("cp.async.wait_group 0;" ::: "memory");
        }
        __syncthreads();   // tile nt visible to all warps

        const float* esb = es + buf * ES_TILE;
        const float* e2b = e2s[buf];

        // ---- 8m x 4n register tile, f32x2 packed along m ----
        unsigned long long acc[4][4];
#pragma unroll
        for (int mp = 0; mp < 4; ++mp)
#pragma unroll
            for (int j = 0; j < 4; ++j) acc[mp][j] = 0ULL;

#pragma unroll 4
        for (int d = 0; d < D; ++d) {
            const float* xrow = xs + d * XPITCH + ty * 8;
            ulonglong2 xA = *(const ulonglong2*)(xrow);       // rows (0,1),(2,3)
            ulonglong2 xB = *(const ulonglong2*)(xrow + 4);   // rows (4,5),(6,7)
            unsigned long long ax[4] = { xA.x, xA.y, xB.x, xB.y };

            float4 e0 = *(const float4*)(esb + d * NT + tx * 4);
            float ev[4] = { e0.x, e0.y, e0.z, e0.w };
#pragma unroll
            for (int j = 0; j < 4; ++j) {
                unsigned long long bv;
                asm("mov.b64 %0, {%1, %1};" : "=l"(bv) : "f"(ev[j]));
#pragma unroll
                for (int mp = 0; mp < 4; ++mp)
                    asm("fma.rn.f32x2 %0, %1, %2, %0;"
                        : "+l"(acc[mp][j]) : "l"(ax[mp]), "l"(bv));
            }
        }

        // ---- distances + running argmin (ascending n, strict < keeps first) ----
#pragma unroll
        for (int j = 0; j < 4; ++j) {
            int n = nt * NT + tx * 4 + j;
            float e2 = e2b[tx * 4 + j];
#pragma unroll
            for (int mp = 0; mp < 4; ++mp) {
                float2 dv = *(float2*)&acc[mp][j];
                // reference association: (||x||^2 + ||e||^2) - 2*dot, one rounding each
                float t0 = rs[ty * 8 + 2 * mp]     + e2;
                float t1 = rs[ty * 8 + 2 * mp + 1] + e2;
                float d0 = fmaf(dv.x, -2.0f, t0);
                float d1 = fmaf(dv.y, -2.0f, t1);
                if (d0 < bestv[2 * mp])     { bestv[2 * mp]     = d0; besti[2 * mp]     = n; }
                if (d1 < bestv[2 * mp + 1]) { bestv[2 * mp + 1] = d1; besti[2 * mp + 1] = n; }
            }
        }
    }

    // ---- cross-thread argmin reduce (reuse es as scratch; 16KB <= 32KB) ----
    __syncthreads();
    float* redv = es;                 // [128][16]
    int*   redi = (int*)(es + 2048);  // [128][16]
#pragma unroll
    for (int i = 0; i < 8; ++i) {
        int m = ty * 8 + i;
        redv[m * 16 + tx] = bestv[i];
        redi[m * 16 + tx] = besti[i];
    }
    __syncthreads();
    if (tid < MT) {
        float bv = redv[tid * 16];
        int   bi = redi[tid * 16];
#pragma unroll
        for (int t = 1; t < 16; ++t) {
            float v = redv[tid * 16 + t];
            int   ii = redi[tid * 16 + t];
            if (v < bv || (v == bv && ii < bi)) { bv = v; bi = ii; }
        }
        idxRow[tid] = bi;
        out[IOFF + p0 + tid] = (float)bi;   // idx as float (output dtype f32)
    }
    __syncthreads();

    // ---- loss (b,h,w,c): 64 contiguous floats per row ----
#pragma unroll
    for (int i = 0; i < 32; ++i) {
        int idx = tid + i * 256;
        int m = idx >> 6, c = idx & 63;
        float xv = xs[c * XPITCH + m];
        float ev = emb[idxRow[m] * D + c];
        float df = ev - xv;                 // (quantized - x), one rounding
        float t  = df * df;
        out[LOFF + (size_t)(p0 + m) * 64 + c] = t + 0.25f * t;  // == round(1.25*t)
    }

    // ---- quantized_out (b,c,h,w): per channel, 128 contiguous floats ----
#pragma unroll
    for (int i = 0; i < 32; ++i) {
        int idx = tid + i * 256;
        int c = idx >> 7, m = idx & 127;
        float xv = xs[c * XPITCH + m];
        float ev = emb[idxRow[m] * D + c];
        // straight-through: x + (q - x), NOT q (last-ulp fidelity to reference)
        out[(size_t)(b * 64 + c) * HW + s0 + m] = xv + (ev - xv);
    }
}

// ---------------------------------------------------------------------------
extern "C" void kernel_launch(void* const* d_in, const int* in_sizes, int n_in,
                              void* d_out, int out_size)
{
    const float* x_in = (const float*)d_in[0];   // inputs  [32,64,64,64]
    const float* emb  = (const float*)d_in[1];   // embedding [1024,64]
    float* out = (float*)d_out;

    static bool attr_set = false;
    // xs: 64*132*4 = 33792B, es: 2*4096*4 = 32768B -> 66560B/CTA (3 CTAs ~= 195KB)
    size_t smem_bytes = (size_t)(D * XPITCH + 2 * ES_TILE) * sizeof(float);
    if (!attr_set) {
        cudaFuncSetAttribute(vq_main_kernel,
                             cudaFuncAttributeMaxDynamicSharedMemorySize,
                             (int)smem_bytes);
        attr_set = true;
    }

    vq_prep_kernel<<<4, 256>>>(emb);
    vq_main_kernel<<<NROWS / MT, 256, smem_bytes>>>(x_in, emb, out);
}